// round 15
// baseline (speedup 1.0000x reference)
#include <cuda_runtime.h>
#include <cuda_fp16.h>
#include <math.h>
#include <stdint.h>

// ---------------- problem constants ----------------
#define BATCH   2
#define SEQL    1024
#define DMODEL  1024
#define DINNER  2048
#define DSTATE  16
#define DCONV   4
#define DTRANK  64
#define NTOK    (BATCH * SEQL)          // 2048
#define XDBL_LD 128                     // padded (dt 0..63 | B 64..79 | C 80..95 | pad)
#define NCHUNK  8
#define CLEN    (SEQL / NCHUNK)         // 128

// ---------------- PTX helpers (portable: sm_80-era features only) ----------------
__device__ __forceinline__ uint32_t smem_to_u32(const void* p) {
    uint32_t a;
    asm("{ .reg .u64 t; cvta.to.shared.u64 t, %1; cvt.u32.u64 %0, t; }" : "=r"(a) : "l"(p));
    return a;
}
__device__ __forceinline__ void cpasync16(uint32_t s, const void* g) {
    asm volatile("cp.async.cg.shared.global [%0], [%1], 16;" :: "r"(s), "l"(g));
}
#define CP_COMMIT()  asm volatile("cp.async.commit_group;" ::: "memory")
#define CP_WAIT0()   asm volatile("cp.async.wait_group 0;" ::: "memory")
#define CP_WAIT1()   asm volatile("cp.async.wait_group 1;" ::: "memory")
#define LDSM4(r, addr) \
    asm volatile("ldmatrix.sync.aligned.m8n8.x4.shared.b16 {%0,%1,%2,%3}, [%4];" \
        : "=r"((r)[0]), "=r"((r)[1]), "=r"((r)[2]), "=r"((r)[3]) : "r"(addr))

__device__ __forceinline__ void mma16816(float* d, const uint32_t* a, const uint32_t* b) {
    asm volatile(
        "mma.sync.aligned.m16n8k16.row.col.f32.f16.f16.f32 "
        "{%0,%1,%2,%3}, {%4,%5,%6,%7}, {%8,%9}, {%0,%1,%2,%3};"
        : "+f"(d[0]), "+f"(d[1]), "+f"(d[2]), "+f"(d[3])
        : "r"(a[0]), "r"(a[1]), "r"(a[2]), "r"(a[3]), "r"(b[0]), "r"(b[1]));
}

// swizzled byte offset of 16B chunk c (0..7) in row r (row = 128 bytes = 8 chunks)
__device__ __forceinline__ uint32_t sw_off(int r, int c) {
    return (uint32_t)(r * 128 + ((c ^ (r & 7)) << 4));
}
__device__ __forceinline__ float silu(float v) { return v / (1.f + __expf(-v)); }

// ---------------- scratch (device globals) ----------------
__device__ __half g_uraw[(size_t)NTOK * DINNER];      // pre-conv u (fp16)
__device__ __half g_zsh[(size_t)NTOK * DINNER];       // silu(z) fp16
__device__ __half g_dh[(size_t)NTOK * DINNER];        // delta fp16
__device__ float  g_xdbl[(size_t)NTOK * XDBL_LD];     // fp32 (B/C for scan)
__device__ float  g_osplit[(size_t)4 * NTOK * DMODEL]; // split-K buffers
// chunked-scan state
__device__ float g_hend[(size_t)BATCH * DINNER * DSTATE * NCHUNK];
__device__ float g_sumd[(size_t)BATCH * DINNER * NCHUNK];

// A-side fp16 (all single-pass)
__device__ __half g_xh[(size_t)NTOK * DMODEL];
__device__ __half g_uh[(size_t)NTOK * DINNER];        // silu(conv(u_raw)) fp16
__device__ __half g_yh[(size_t)NTOK * DINNER];
__device__ __half g_dth[(size_t)NTOK * DTRANK];
// B-side: transposed single fp16 weights: [N][K] row-major (K contiguous)
__device__ __half g_wint[(size_t)2 * DINNER * DMODEL];
__device__ __half g_wxt[(size_t)XDBL_LD * DINNER];
__device__ __half g_wdtt[(size_t)DINNER * DTRANK];
__device__ __half g_wot[(size_t)DMODEL * DINNER];

// ---------------- mma.sync fp16 GEMM, K-tile 64 ----------------
// C[M,N] = Ah[M,K] @ B[K,N], B given transposed [N][K], fp32 accum. Single-pass A.
// 3-stage pipeline, 32KB stages, 1 barrier/iter, prefetch BEFORE compute
// (2-iteration prefetch distance; target stage's last readers were iter it-1,
//  all of whom passed the barrier at iter it).
// EPI 0: store fp32 to C (+zstride per blockIdx.z)
// EPI 1: softplus(acc+bias) -> fp16 g_dh
// EPI 3: u-half -> fp16 g_uraw; z-half -> silu -> fp16 g_zsh
#define MG_SMEM 98304
template <int EPI>
__global__ __launch_bounds__(256, 2) void mma_gemm(
    const __half* __restrict__ Ah, int lda,
    const __half* __restrict__ B, int ldb,
    float* __restrict__ C, int ldc, int K, int KS, const float* __restrict__ bias,
    int zstride)
{
    extern __shared__ char smem[];
    uint32_t sb = smem_to_u32(smem);
    const uint32_t SSZ = 32768u, B_OFF = 16384u;
    const int NST = 3;
    const int tid = threadIdx.x, lane = tid & 31, wid = tid >> 5;
    const int wm = wid & 3, wn = wid >> 2;          // warp tile: rows wm*32, cols wn*64
    const int row0 = blockIdx.y * 128, col0 = blockIdx.x * 128;
    const int kper = K / KS;
    const int kbeg = blockIdx.z * kper;
    const int kn = kper >> 6;                        // 64-wide k tiles

    float acc[2][8][4];
#pragma unroll
    for (int i = 0; i < 2; i++)
#pragma unroll
        for (int j = 0; j < 8; j++)
#pragma unroll
            for (int r = 0; r < 4; r++) acc[i][j][r] = 0.f;

    auto load_stage = [&](int s, int k0) {
        uint32_t base = sb + s * SSZ;
#pragma unroll
        for (int j = 0; j < 4; j++) {
            int idx = tid + j * 256;                 // 0..1023
            int r = idx >> 3, c = idx & 7;
            uint32_t so = sw_off(r, c);
            cpasync16(base + so,         Ah + (size_t)(row0 + r) * lda + k0 + c * 8);
            cpasync16(base + B_OFF + so, B  + (size_t)(col0 + r) * ldb + k0 + c * 8);
        }
        CP_COMMIT();
    };

    load_stage(0, kbeg);
    if (kn > 1) load_stage(1, kbeg + 64);

    const int a_row = wm * 32 + ((lane >> 3) & 1) * 8 + (lane & 7);   // + mi*16
    const int b_row = wn * 64 + (lane >> 4) * 8 + (lane & 7);         // + j*16

    for (int it = 0; it < kn; it++) {
        if (it + 1 < kn) CP_WAIT1(); else CP_WAIT0();
        __syncthreads();
        if (it + 2 < kn) load_stage((it + 2) % NST, kbeg + (it + 2) * 64);
        uint32_t base = sb + (it % NST) * SSZ;
#pragma unroll
        for (int kk = 0; kk < 4; kk++) {
            uint32_t ah[2][4], bb[8][2];
#pragma unroll
            for (int mi = 0; mi < 2; mi++) {
                int r = a_row + mi * 16;
                int c = kk * 2 + (lane >> 4);
                LDSM4(ah[mi], base + sw_off(r, c));
            }
#pragma unroll
            for (int j = 0; j < 4; j++) {
                int r = b_row + j * 16;
                int c = kk * 2 + ((lane >> 3) & 1);
                uint32_t t[4];
                LDSM4(t, base + B_OFF + sw_off(r, c));
                bb[2 * j][0] = t[0]; bb[2 * j][1] = t[1];
                bb[2 * j + 1][0] = t[2]; bb[2 * j + 1][1] = t[3];
            }
#pragma unroll
            for (int mi = 0; mi < 2; mi++)
#pragma unroll
                for (int nj = 0; nj < 8; nj++)
                    mma16816(acc[mi][nj], ah[mi], bb[nj]);
        }
    }

    if (EPI == 0) C += (size_t)blockIdx.z * zstride;

#pragma unroll
    for (int mi = 0; mi < 2; mi++) {
        int row = row0 + wm * 32 + mi * 16 + (lane >> 2);
#pragma unroll
        for (int nj = 0; nj < 8; nj++) {
            int col = col0 + wn * 64 + nj * 8 + (lane & 3) * 2;
            float* a = acc[mi][nj];
            if (EPI == 0) {
                *(float2*)&C[(size_t)row * ldc + col]       = make_float2(a[0], a[1]);
                *(float2*)&C[(size_t)(row + 8) * ldc + col] = make_float2(a[2], a[3]);
            } else if (EPI == 1) {
                float b0 = bias[col], b1 = bias[col + 1];
                float v0 = a[0] + b0, v1 = a[1] + b1, v2 = a[2] + b0, v3 = a[3] + b1;
                v0 = (v0 > 20.f) ? v0 : __logf(1.f + __expf(v0));
                v1 = (v1 > 20.f) ? v1 : __logf(1.f + __expf(v1));
                v2 = (v2 > 20.f) ? v2 : __logf(1.f + __expf(v2));
                v3 = (v3 > 20.f) ? v3 : __logf(1.f + __expf(v3));
                *(__half2*)&g_dh[(size_t)row * DINNER + col] =
                    __halves2half2(__float2half_rn(v0), __float2half_rn(v1));
                *(__half2*)&g_dh[(size_t)(row + 8) * DINNER + col] =
                    __halves2half2(__float2half_rn(v2), __float2half_rn(v3));
            } else {  // EPI == 3
                if (col < DINNER) {
                    *(__half2*)&g_uraw[(size_t)row * DINNER + col] =
                        __halves2half2(__float2half_rn(a[0]), __float2half_rn(a[1]));
                    *(__half2*)&g_uraw[(size_t)(row + 8) * DINNER + col] =
                        __halves2half2(__float2half_rn(a[2]), __float2half_rn(a[3]));
                } else {
                    int zc = col - DINNER;
                    *(__half2*)&g_zsh[(size_t)row * DINNER + zc] =
                        __halves2half2(__float2half_rn(silu(a[0])), __float2half_rn(silu(a[1])));
                    *(__half2*)&g_zsh[(size_t)(row + 8) * DINNER + zc] =
                        __halves2half2(__float2half_rn(silu(a[2])), __float2half_rn(silu(a[3])));
                }
            }
        }
    }
}

// ---------------- reduce 2 split-K buffers into out ----------------
__global__ void reduce2(const float* __restrict__ src, float* __restrict__ dst, int n4) {
    int i = blockIdx.x * blockDim.x + threadIdx.x;
    if (i >= n4) return;
    const float4* s = (const float4*)src;
    float4 a = s[i], b = s[i + n4];
    ((float4*)dst)[i] = make_float4(a.x + b.x, a.y + b.y, a.z + b.z, a.w + b.w);
}

// ---------------- reduce 8 split-K xdbl buffers -> g_xdbl (fp32) + dt hi ----------------
__global__ void reduce8_xdbl(const float* __restrict__ src) {
    int i = blockIdx.x * blockDim.x + threadIdx.x;   // < NTOK*XDBL_LD/4
    const int n4 = NTOK * XDBL_LD / 4;
    if (i >= n4) return;
    const float4* s = (const float4*)src;
    float4 r = s[i];
#pragma unroll
    for (int k = 1; k < 8; k++) {
        float4 v = s[i + k * n4];
        r.x += v.x; r.y += v.y; r.z += v.z; r.w += v.w;
    }
    ((float4*)g_xdbl)[i] = r;
    int t  = i >> 5;          // row (32 float4 chunks per 128-col row)
    int cq = i & 31;
    if (cq < DTRANK / 4) {    // dt region -> fp16 hi
        int c = cq * 4;
        size_t o = (size_t)t * DTRANK + c;
        *(__half2*)&g_dth[o]     = __halves2half2(__float2half_rn(r.x), __float2half_rn(r.y));
        *(__half2*)&g_dth[o + 2] = __halves2half2(__float2half_rn(r.z), __float2half_rn(r.w));
    }
}

// ---------------- transpose body (shared) ----------------
__device__ __forceinline__ void trans_body(const float* __restrict__ W, int K, int N,
                                           __half* __restrict__ T, int bx, int by,
                                           float t[32][33])
{
    int tx = threadIdx.x, ty0 = threadIdx.y;
#pragma unroll
    for (int s = 0; s < 4; s++) {
        int ty = ty0 + s * 8;
        int col = bx * 32 + tx;          // n
        int row = by * 32 + ty;          // k
        t[ty][tx] = (col < N) ? W[(size_t)row * N + col] : 0.f;
    }
    __syncthreads();
#pragma unroll
    for (int s = 0; s < 4; s++) {
        int ty = ty0 + s * 8;
        int n = bx * 32 + ty;
        int k = by * 32 + tx;
        T[(size_t)n * K + k] = __float2half_rn(t[tx][ty]);
    }
}

// ---------------- ONE prep kernel: cvt_h(x) + all 4 weight transposes ----------------
__global__ void prep_all(const float* __restrict__ x,
                         const float* __restrict__ Win, const float* __restrict__ Wout,
                         const float* __restrict__ Wx,  const float* __restrict__ Wdt)
{
    __shared__ float t[32][33];
    int bid = blockIdx.x;
    if (bid < 2048) {
        int i = bid * 256 + threadIdx.y * 32 + threadIdx.x;   // < 524288 = NTOK*DMODEL/4
        float4 v = ((const float4*)x)[i];
        ((__half2*)g_xh)[i * 2]     = __halves2half2(__float2half_rn(v.x), __float2half_rn(v.y));
        ((__half2*)g_xh)[i * 2 + 1] = __halves2half2(__float2half_rn(v.z), __float2half_rn(v.w));
        return;
    }
    bid -= 2048;
    if (bid < 4096) { trans_body(Win, DMODEL, 2 * DINNER, g_wint, bid & 127, bid >> 7, t); return; }
    bid -= 4096;
    if (bid < 2048) { trans_body(Wout, DINNER, DMODEL, g_wot, bid & 31, bid >> 5, t); return; }
    bid -= 2048;
    if (bid < 256)  { trans_body(Wx, DINNER, DTRANK + 2 * DSTATE, g_wxt, bid & 3, bid >> 2, t); return; }
    bid -= 256;
    trans_body(Wdt, DTRANK, DINNER, g_wdtt, bid & 63, bid >> 6, t);
}

// ---------------- conv + SiLU -> fp16 uh, 4 channels/thread, fp16 inputs ----------------
__global__ void conv_silu(const float* __restrict__ ck, const float* __restrict__ cb)
{
    int idx = blockIdx.x * blockDim.x + threadIdx.x;   // < NTOK*DINNER/4
    if (idx >= NTOK * DINNER / 4) return;
    int dq = idx & (DINNER / 4 - 1);
    int bt = idx >> 9;
    int t  = bt & (SEQL - 1);
    int d  = dq * 4;

    float4 acc = *(const float4*)&cb[d];
#pragma unroll
    for (int w = 0; w < DCONV; w++) {
        int tt = t - (DCONV - 1) + w;
        if (tt >= 0) {
            float4 k = *(const float4*)&ck[w * DINNER + d];
            const __half2* up = (const __half2*)&g_uraw[(size_t)(bt - (DCONV - 1) + w) * DINNER + d];
            float2 v0 = __half22float2(up[0]);
            float2 v1 = __half22float2(up[1]);
            acc.x = fmaf(k.x, v0.x, acc.x);
            acc.y = fmaf(k.y, v0.y, acc.y);
            acc.z = fmaf(k.z, v1.x, acc.z);
            acc.w = fmaf(k.w, v1.y, acc.w);
        }
    }
    size_t o = (size_t)bt * DINNER + d;
    *(__half2*)&g_uh[o]     = __halves2half2(__float2half_rn(silu(acc.x)), __float2half_rn(silu(acc.y)));
    *(__half2*)&g_uh[o + 2] = __halves2half2(__float2half_rn(silu(acc.z)), __float2half_rn(silu(acc.w)));
}

// ---------------- chunked scan: phase 1 (chunk end-states, h0=0), smem B ----------------
__global__ __launch_bounds__(256) void scan_phase1(const float* __restrict__ A_log)
{
    __shared__ float sB[CLEN * DSTATE];    // 8 KB
    int tid = threadIdx.x;
    int ch = blockIdx.x * 16 + (tid >> 4);   // 0..4095
    int n = tid & 15;
    int c = blockIdx.y;
    int b = ch >> 11;
    int d = ch & (DINNER - 1);

    const float* xd = g_xdbl + (size_t)(b * SEQL + c * CLEN) * XDBL_LD;
    for (int i = tid; i < CLEN * DSTATE; i += 256)
        sB[i] = xd[(i >> 4) * XDBL_LD + DTRANK + (i & 15)];
    __syncthreads();

    float a = -expf(A_log[d * DSTATE + n]);
    float h = 0.f, sd = 0.f;

    const __half* dptr = g_dh + (size_t)(b * SEQL + c * CLEN) * DINNER + d;
    const __half* uptr = g_uh + (size_t)(b * SEQL + c * CLEN) * DINNER + d;

    for (int t = 0; t < CLEN; t++) {
        float delta = __half2float(dptr[(size_t)t * DINNER]);
        float uv    = __half2float(uptr[(size_t)t * DINNER]);
        float Bn    = sB[(t << 4) | n];
        h = __expf(delta * a) * h + delta * uv * Bn;
        sd += delta;
    }
    size_t idx = ((size_t)(b * DINNER + d) * DSTATE + n);
    g_hend[idx * NCHUNK + c] = h;
    if (n == 0) g_sumd[(size_t)(b * DINNER + d) * NCHUNK + c] = sd;
}

// ---------------- chunked scan: phase 2 (inline combine + y), smem B+C ----------------
__global__ __launch_bounds__(256) void scan_phase2(
    const float* __restrict__ A_log, const float* __restrict__ Dp)
{
    __shared__ float sBC[CLEN * 2 * DSTATE];   // 16 KB: [t][0..15]=B, [t][16..31]=C
    int tid = threadIdx.x;
    int ch = blockIdx.x * 16 + (tid >> 4);
    int n = tid & 15;
    int c = blockIdx.y;
    int b = ch >> 11;
    int d = ch & (DINNER - 1);

    const float* xd = g_xdbl + (size_t)(b * SEQL + c * CLEN) * XDBL_LD;
    for (int i = tid; i < CLEN * 2 * DSTATE; i += 256)
        sBC[i] = xd[(i >> 5) * XDBL_LD + DTRANK + (i & 31)];
    __syncthreads();

    float a = -expf(A_log[d * DSTATE + n]);
    float Dd = Dp[d];

    // inline combine: h0 for this chunk = fold of previous chunks
    float h = 0.f;
    {
        size_t bi = ((size_t)(b * DINNER + d) * DSTATE + n) * NCHUNK;
        size_t bs = (size_t)(b * DINNER + d) * NCHUNK;
        for (int cc = 0; cc < c; cc++)
            h = __expf(a * g_sumd[bs + cc]) * h + g_hend[bi + cc];
    }

    const __half* dptr = g_dh  + (size_t)(b * SEQL + c * CLEN) * DINNER + d;
    const __half* uptr = g_uh  + (size_t)(b * SEQL + c * CLEN) * DINNER + d;
    const __half* zptr = g_zsh + (size_t)(b * SEQL + c * CLEN) * DINNER + d;
    __half* yh = g_yh + (size_t)(b * SEQL + c * CLEN) * DINNER + d;

    for (int t = 0; t < CLEN; t++) {
        float delta = __half2float(dptr[(size_t)t * DINNER]);
        float uv    = __half2float(uptr[(size_t)t * DINNER]);
        float Bn    = sBC[(t << 5) | n];
        float Cn    = sBC[(t << 5) | 16 | n];

        h = __expf(delta * a) * h + delta * uv * Bn;

        float p = h * Cn;
        p += __shfl_xor_sync(0xffffffffu, p, 8);
        p += __shfl_xor_sync(0xffffffffu, p, 4);
        p += __shfl_xor_sync(0xffffffffu, p, 2);
        p += __shfl_xor_sync(0xffffffffu, p, 1);

        if (n == 0) {
            float v = (p + uv * Dd) * __half2float(zptr[(size_t)t * DINNER]);
            yh[(size_t)t * DINNER] = __float2half_rn(v);
        }
    }
}

// ---------------- launch ----------------
extern "C" void kernel_launch(void* const* d_in, const int* in_sizes, int n_in,
                              void* d_out, int out_size)
{
    (void)in_sizes; (void)n_in; (void)out_size;
    const float* x     = (const float*)d_in[0];
    const float* W_in  = (const float*)d_in[1];
    const float* ck    = (const float*)d_in[2];
    const float* cb    = (const float*)d_in[3];
    const float* W_x   = (const float*)d_in[4];
    const float* W_dt  = (const float*)d_in[5];
    const float* b_dt  = (const float*)d_in[6];
    const float* W_out = (const float*)d_in[7];
    const float* A_log = (const float*)d_in[8];
    const float* Dp    = (const float*)d_in[9];
    float* out = (float*)d_out;

    cudaFuncSetAttribute((const void*)mma_gemm<0>, cudaFuncAttributeMaxDynamicSharedMemorySize, MG_SMEM);
    cudaFuncSetAttribute((const void*)mma_gemm<1>, cudaFuncAttributeMaxDynamicSharedMemorySize, MG_SMEM);
    cudaFuncSetAttribute((const void*)mma_gemm<3>, cudaFuncAttributeMaxDynamicSharedMemorySize, MG_SMEM);

    float *p_osplit;
    cudaGetSymbolAddress((void**)&p_osplit, g_osplit);
    __half *xh, *uh, *yh, *dth;
    __half *wint, *wxt, *wdtt, *wot;
    cudaGetSymbolAddress((void**)&xh, g_xh);
    cudaGetSymbolAddress((void**)&uh, g_uh);
    cudaGetSymbolAddress((void**)&yh, g_yh);
    cudaGetSymbolAddress((void**)&dth, g_dth);
    cudaGetSymbolAddress((void**)&wint, g_wint);
    cudaGetSymbolAddress((void**)&wxt, g_wxt);
    cudaGetSymbolAddress((void**)&wdtt, g_wdtt);
    cudaGetSymbolAddress((void**)&wot, g_wot);

    // 1: ALL prep (cvt x + 4 weight transposes)
    prep_all<<<8576, dim3(32, 8)>>>(x, W_in, W_out, W_x, W_dt);

    // 2: xz = x @ W_in : M=2048, N=4096, K=1024; u-half -> fp16 g_uraw, z -> silu -> g_zsh
    mma_gemm<3><<<dim3(32, 16, 1), 256, MG_SMEM>>>(
        xh, DMODEL, wint, DMODEL, nullptr, 0, DMODEL, 1, nullptr, 0);

    // 3: conv + silu -> fp16 uh
    conv_silu<<<(NTOK * DINNER / 4) / 256, 256>>>(ck, cb);

    // 4: x_dbl = u @ W_x : M=2048, N=128(pad of 96), K=2048, split-K=8 -> fused reduce
    mma_gemm<0><<<dim3(1, 16, 8), 256, MG_SMEM>>>(
        uh, DINNER, wxt, DINNER, p_osplit, XDBL_LD, DINNER, 8, nullptr, NTOK * XDBL_LD);
    // 5:
    reduce8_xdbl<<<(NTOK * XDBL_LD / 4 + 255) / 256, 256>>>(p_osplit);

    // 6: delta = softplus(dt_lo @ W_dt + b_dt) : M=2048, N=2048, K=64 -> fp16 g_dh
    mma_gemm<1><<<dim3(16, 16, 1), 256, MG_SMEM>>>(
        dth, DTRANK, wdtt, DTRANK, nullptr, 0, DTRANK, 1, b_dt, 0);

    // 7,8: chunked selective scan (combine folded into phase 2)
    scan_phase1<<<dim3((BATCH * DINNER) / 16, NCHUNK), 256>>>(A_log);
    scan_phase2<<<dim3((BATCH * DINNER) / 16, NCHUNK), 256>>>(A_log, Dp);

    // 9,10: out = y @ W_out : M=2048, N=1024, K=2048, split-K=2 -> reduce
    mma_gemm<0><<<dim3(8, 16, 2), 256, MG_SMEM>>>(
        yh, DINNER, wot, DINNER, p_osplit, DMODEL, DINNER, 2, nullptr, NTOK * DMODEL);
    reduce2<<<(NTOK * DMODEL / 4 + 255) / 256, 256>>>(p_osplit, out, NTOK * DMODEL / 4);
}

// round 16
// speedup vs baseline: 1.0299x; 1.0299x over previous
#include <cuda_runtime.h>
#include <cuda_fp16.h>
#include <math.h>
#include <stdint.h>

// ---------------- problem constants ----------------
#define BATCH   2
#define SEQL    1024
#define DMODEL  1024
#define DINNER  2048
#define DSTATE  16
#define DCONV   4
#define DTRANK  64
#define NTOK    (BATCH * SEQL)          // 2048
#define XDBL_LD 128                     // padded (dt 0..63 | B 64..79 | C 80..95 | pad)
#define NCHUNK  8
#define CLEN    (SEQL / NCHUNK)         // 128

// ---------------- PTX helpers (portable: sm_80-era features only) ----------------
__device__ __forceinline__ uint32_t smem_to_u32(const void* p) {
    uint32_t a;
    asm("{ .reg .u64 t; cvta.to.shared.u64 t, %1; cvt.u32.u64 %0, t; }" : "=r"(a) : "l"(p));
    return a;
}
__device__ __forceinline__ void cpasync16(uint32_t s, const void* g) {
    asm volatile("cp.async.cg.shared.global [%0], [%1], 16;" :: "r"(s), "l"(g));
}
#define CP_COMMIT()  asm volatile("cp.async.commit_group;" ::: "memory")
#define CP_WAIT0()   asm volatile("cp.async.wait_group 0;" ::: "memory")
#define CP_WAIT1()   asm volatile("cp.async.wait_group 1;" ::: "memory")
#define LDSM4(r, addr) \
    asm volatile("ldmatrix.sync.aligned.m8n8.x4.shared.b16 {%0,%1,%2,%3}, [%4];" \
        : "=r"((r)[0]), "=r"((r)[1]), "=r"((r)[2]), "=r"((r)[3]) : "r"(addr))

__device__ __forceinline__ void mma16816(float* d, const uint32_t* a, const uint32_t* b) {
    asm volatile(
        "mma.sync.aligned.m16n8k16.row.col.f32.f16.f16.f32 "
        "{%0,%1,%2,%3}, {%4,%5,%6,%7}, {%8,%9}, {%0,%1,%2,%3};"
        : "+f"(d[0]), "+f"(d[1]), "+f"(d[2]), "+f"(d[3])
        : "r"(a[0]), "r"(a[1]), "r"(a[2]), "r"(a[3]), "r"(b[0]), "r"(b[1]));
}

// swizzled byte offset of 16B chunk c (0..7) in row r (row = 128 bytes = 8 chunks)
__device__ __forceinline__ uint32_t sw_off(int r, int c) {
    return (uint32_t)(r * 128 + ((c ^ (r & 7)) << 4));
}
__device__ __forceinline__ float silu(float v) { return v / (1.f + __expf(-v)); }

// ---------------- scratch (device globals) ----------------
__device__ __half g_uraw[(size_t)NTOK * DINNER];      // pre-conv u (fp16)
__device__ __half g_zsh[(size_t)NTOK * DINNER];       // silu(z) fp16
__device__ __half g_dh[(size_t)NTOK * DINNER];        // delta fp16
__device__ float  g_xdbl[(size_t)NTOK * XDBL_LD];     // fp32 (B/C for scan)
__device__ float  g_osplit[(size_t)4 * NTOK * DMODEL]; // split-K buffers
// chunked-scan state
__device__ float g_hend[(size_t)BATCH * DINNER * DSTATE * NCHUNK];
__device__ float g_sumd[(size_t)BATCH * DINNER * NCHUNK];

// A-side fp16 (all single-pass)
__device__ __half g_xh[(size_t)NTOK * DMODEL];
__device__ __half g_uh[(size_t)NTOK * DINNER];        // silu(conv(u_raw)) fp16
__device__ __half g_yh[(size_t)NTOK * DINNER];
__device__ __half g_dth[(size_t)NTOK * DTRANK];
// B-side: transposed single fp16 weights: [N][K] row-major (K contiguous)
__device__ __half g_wint[(size_t)2 * DINNER * DMODEL];
__device__ __half g_wxt[(size_t)XDBL_LD * DINNER];
__device__ __half g_wdtt[(size_t)DINNER * DTRANK];
__device__ __half g_wot[(size_t)DMODEL * DINNER];

// ---------------- mma.sync fp16 GEMM, K-tile 64 (R14 mainloop layout) ----------------
// C[M,N] = Ah[M,K] @ B[K,N], B given transposed [N][K], fp32 accum. Single-pass A.
// 3-stage pipeline, 32KB stages, 1 barrier/iter, prefetch issued after compute.
// EPI 0: store fp32 to C (+zstride per blockIdx.z)
// EPI 1: softplus(acc+bias) -> fp16 g_dh
// EPI 3: u-half -> fp16 g_uraw; z-half -> silu -> fp16 g_zsh
#define MG_SMEM 98304
template <int EPI>
__global__ __launch_bounds__(256, 2) void mma_gemm(
    const __half* __restrict__ Ah, int lda,
    const __half* __restrict__ B, int ldb,
    float* __restrict__ C, int ldc, int K, int KS, const float* __restrict__ bias,
    int zstride)
{
    extern __shared__ char smem[];
    uint32_t sb = smem_to_u32(smem);
    const uint32_t SSZ = 32768u, B_OFF = 16384u;
    const int NST = 3;
    const int tid = threadIdx.x, lane = tid & 31, wid = tid >> 5;
    const int wm = wid & 3, wn = wid >> 2;          // warp tile: rows wm*32, cols wn*64
    const int row0 = blockIdx.y * 128, col0 = blockIdx.x * 128;
    const int kper = K / KS;
    const int kbeg = blockIdx.z * kper;
    const int kn = kper >> 6;                        // 64-wide k tiles

    float acc[2][8][4];
#pragma unroll
    for (int i = 0; i < 2; i++)
#pragma unroll
        for (int j = 0; j < 8; j++)
#pragma unroll
            for (int r = 0; r < 4; r++) acc[i][j][r] = 0.f;

    auto load_stage = [&](int s, int k0) {
        uint32_t base = sb + s * SSZ;
#pragma unroll
        for (int j = 0; j < 4; j++) {
            int idx = tid + j * 256;                 // 0..1023
            int r = idx >> 3, c = idx & 7;
            uint32_t so = sw_off(r, c);
            cpasync16(base + so,         Ah + (size_t)(row0 + r) * lda + k0 + c * 8);
            cpasync16(base + B_OFF + so, B  + (size_t)(col0 + r) * ldb + k0 + c * 8);
        }
        CP_COMMIT();
    };

    load_stage(0, kbeg);
    if (kn > 1) load_stage(1, kbeg + 64);

    const int a_row = wm * 32 + ((lane >> 3) & 1) * 8 + (lane & 7);   // + mi*16
    const int b_row = wn * 64 + (lane >> 4) * 8 + (lane & 7);         // + j*16

    for (int it = 0; it < kn; it++) {
        if (it + 1 < kn) CP_WAIT1(); else CP_WAIT0();
        __syncthreads();
        uint32_t base = sb + (it % NST) * SSZ;
#pragma unroll
        for (int kk = 0; kk < 4; kk++) {
            uint32_t ah[2][4], bb[8][2];
#pragma unroll
            for (int mi = 0; mi < 2; mi++) {
                int r = a_row + mi * 16;
                int c = kk * 2 + (lane >> 4);
                LDSM4(ah[mi], base + sw_off(r, c));
            }
#pragma unroll
            for (int j = 0; j < 4; j++) {
                int r = b_row + j * 16;
                int c = kk * 2 + ((lane >> 3) & 1);
                uint32_t t[4];
                LDSM4(t, base + B_OFF + sw_off(r, c));
                bb[2 * j][0] = t[0]; bb[2 * j][1] = t[1];
                bb[2 * j + 1][0] = t[2]; bb[2 * j + 1][1] = t[3];
            }
#pragma unroll
            for (int mi = 0; mi < 2; mi++)
#pragma unroll
                for (int nj = 0; nj < 8; nj++)
                    mma16816(acc[mi][nj], ah[mi], bb[nj]);
        }
        if (it + 2 < kn) load_stage((it + 2) % NST, kbeg + (it + 2) * 64);
        // 3-stage: load target (it+2)%3 != it%3 (current readers) and its last
        // readers (iter it-1) passed the barrier above. Safe with one barrier.
    }

    if (EPI == 0) C += (size_t)blockIdx.z * zstride;

#pragma unroll
    for (int mi = 0; mi < 2; mi++) {
        int row = row0 + wm * 32 + mi * 16 + (lane >> 2);
#pragma unroll
        for (int nj = 0; nj < 8; nj++) {
            int col = col0 + wn * 64 + nj * 8 + (lane & 3) * 2;
            float* a = acc[mi][nj];
            if (EPI == 0) {
                *(float2*)&C[(size_t)row * ldc + col]       = make_float2(a[0], a[1]);
                *(float2*)&C[(size_t)(row + 8) * ldc + col] = make_float2(a[2], a[3]);
            } else if (EPI == 1) {
                float b0 = bias[col], b1 = bias[col + 1];
                float v0 = a[0] + b0, v1 = a[1] + b1, v2 = a[2] + b0, v3 = a[3] + b1;
                v0 = (v0 > 20.f) ? v0 : __logf(1.f + __expf(v0));
                v1 = (v1 > 20.f) ? v1 : __logf(1.f + __expf(v1));
                v2 = (v2 > 20.f) ? v2 : __logf(1.f + __expf(v2));
                v3 = (v3 > 20.f) ? v3 : __logf(1.f + __expf(v3));
                *(__half2*)&g_dh[(size_t)row * DINNER + col] =
                    __halves2half2(__float2half_rn(v0), __float2half_rn(v1));
                *(__half2*)&g_dh[(size_t)(row + 8) * DINNER + col] =
                    __halves2half2(__float2half_rn(v2), __float2half_rn(v3));
            } else {  // EPI == 3
                if (col < DINNER) {
                    *(__half2*)&g_uraw[(size_t)row * DINNER + col] =
                        __halves2half2(__float2half_rn(a[0]), __float2half_rn(a[1]));
                    *(__half2*)&g_uraw[(size_t)(row + 8) * DINNER + col] =
                        __halves2half2(__float2half_rn(a[2]), __float2half_rn(a[3]));
                } else {
                    int zc = col - DINNER;
                    *(__half2*)&g_zsh[(size_t)row * DINNER + zc] =
                        __halves2half2(__float2half_rn(silu(a[0])), __float2half_rn(silu(a[1])));
                    *(__half2*)&g_zsh[(size_t)(row + 8) * DINNER + zc] =
                        __halves2half2(__float2half_rn(silu(a[2])), __float2half_rn(silu(a[3])));
                }
            }
        }
    }
}

// ---------------- reduce 4 split-K buffers into out ----------------
__global__ void reduce4(const float* __restrict__ src, float* __restrict__ dst, int n4) {
    int i = blockIdx.x * blockDim.x + threadIdx.x;
    if (i >= n4) return;
    const float4* s = (const float4*)src;
    float4 a = s[i], b = s[i + n4], c = s[i + 2 * n4], d = s[i + 3 * n4];
    float4 r = make_float4(a.x + b.x + c.x + d.x, a.y + b.y + c.y + d.y,
                           a.z + b.z + c.z + d.z, a.w + b.w + c.w + d.w);
    ((float4*)dst)[i] = r;
}

// ---------------- reduce 8 split-K xdbl buffers -> g_xdbl (fp32) + dt hi ----------------
__global__ void reduce8_xdbl(const float* __restrict__ src) {
    int i = blockIdx.x * blockDim.x + threadIdx.x;   // < NTOK*XDBL_LD/4
    const int n4 = NTOK * XDBL_LD / 4;
    if (i >= n4) return;
    const float4* s = (const float4*)src;
    float4 r = s[i];
#pragma unroll
    for (int k = 1; k < 8; k++) {
        float4 v = s[i + k * n4];
        r.x += v.x; r.y += v.y; r.z += v.z; r.w += v.w;
    }
    ((float4*)g_xdbl)[i] = r;
    int t  = i >> 5;          // row (32 float4 chunks per 128-col row)
    int cq = i & 31;
    if (cq < DTRANK / 4) {    // dt region -> fp16 hi
        int c = cq * 4;
        size_t o = (size_t)t * DTRANK + c;
        *(__half2*)&g_dth[o]     = __halves2half2(__float2half_rn(r.x), __float2half_rn(r.y));
        *(__half2*)&g_dth[o + 2] = __halves2half2(__float2half_rn(r.z), __float2half_rn(r.w));
    }
}

// ---------------- transpose body (shared) ----------------
__device__ __forceinline__ void trans_body(const float* __restrict__ W, int K, int N,
                                           __half* __restrict__ T, int bx, int by,
                                           float t[32][33])
{
    int tx = threadIdx.x, ty0 = threadIdx.y;
#pragma unroll
    for (int s = 0; s < 4; s++) {
        int ty = ty0 + s * 8;
        int col = bx * 32 + tx;          // n
        int row = by * 32 + ty;          // k
        t[ty][tx] = (col < N) ? W[(size_t)row * N + col] : 0.f;
    }
    __syncthreads();
#pragma unroll
    for (int s = 0; s < 4; s++) {
        int ty = ty0 + s * 8;
        int n = bx * 32 + ty;
        int k = by * 32 + tx;
        T[(size_t)n * K + k] = __float2half_rn(t[tx][ty]);
    }
}

// ---------------- ONE prep kernel: cvt_h(x) + all 4 weight transposes ----------------
__global__ void prep_all(const float* __restrict__ x,
                         const float* __restrict__ Win, const float* __restrict__ Wout,
                         const float* __restrict__ Wx,  const float* __restrict__ Wdt)
{
    __shared__ float t[32][33];
    int bid = blockIdx.x;
    if (bid < 2048) {
        int i = bid * 256 + threadIdx.y * 32 + threadIdx.x;   // < 524288 = NTOK*DMODEL/4
        float4 v = ((const float4*)x)[i];
        ((__half2*)g_xh)[i * 2]     = __halves2half2(__float2half_rn(v.x), __float2half_rn(v.y));
        ((__half2*)g_xh)[i * 2 + 1] = __halves2half2(__float2half_rn(v.z), __float2half_rn(v.w));
        return;
    }
    bid -= 2048;
    if (bid < 4096) { trans_body(Win, DMODEL, 2 * DINNER, g_wint, bid & 127, bid >> 7, t); return; }
    bid -= 4096;
    if (bid < 2048) { trans_body(Wout, DINNER, DMODEL, g_wot, bid & 31, bid >> 5, t); return; }
    bid -= 2048;
    if (bid < 256)  { trans_body(Wx, DINNER, DTRANK + 2 * DSTATE, g_wxt, bid & 3, bid >> 2, t); return; }
    bid -= 256;
    trans_body(Wdt, DTRANK, DINNER, g_wdtt, bid & 63, bid >> 6, t);
}

// ---------------- conv + SiLU -> fp16 uh, 8 channels/thread, uint4 fp16 loads ----------------
__global__ void conv_silu(const float* __restrict__ ck, const float* __restrict__ cb)
{
    int idx = blockIdx.x * blockDim.x + threadIdx.x;   // < NTOK*DINNER/8
    if (idx >= NTOK * DINNER / 8) return;
    int dq = idx & (DINNER / 8 - 1);
    int bt = idx >> 8;
    int t  = bt & (SEQL - 1);
    int d  = dq * 8;

    float acc[8];
#pragma unroll
    for (int j = 0; j < 2; j++) {
        float4 b = *(const float4*)&cb[d + j * 4];
        acc[j * 4 + 0] = b.x; acc[j * 4 + 1] = b.y; acc[j * 4 + 2] = b.z; acc[j * 4 + 3] = b.w;
    }
#pragma unroll
    for (int w = 0; w < DCONV; w++) {
        int tt = t - (DCONV - 1) + w;
        if (tt >= 0) {
            uint4 uv = *(const uint4*)&g_uraw[(size_t)(bt - (DCONV - 1) + w) * DINNER + d];
            const __half2* up = (const __half2*)&uv;
#pragma unroll
            for (int j = 0; j < 2; j++) {
                float4 k = *(const float4*)&ck[w * DINNER + d + j * 4];
                float2 v0 = __half22float2(up[j * 2]);
                float2 v1 = __half22float2(up[j * 2 + 1]);
                acc[j * 4 + 0] = fmaf(k.x, v0.x, acc[j * 4 + 0]);
                acc[j * 4 + 1] = fmaf(k.y, v0.y, acc[j * 4 + 1]);
                acc[j * 4 + 2] = fmaf(k.z, v1.x, acc[j * 4 + 2]);
                acc[j * 4 + 3] = fmaf(k.w, v1.y, acc[j * 4 + 3]);
            }
        }
    }
    uint4 o4;
    __half2* op = (__half2*)&o4;
#pragma unroll
    for (int j = 0; j < 4; j++)
        op[j] = __halves2half2(__float2half_rn(silu(acc[j * 2])),
                               __float2half_rn(silu(acc[j * 2 + 1])));
    *(uint4*)&g_uh[(size_t)bt * DINNER + d] = o4;
}

// ---------------- chunked scan: phase 1 (chunk end-states, h0=0), smem B ----------------
__global__ __launch_bounds__(256) void scan_phase1(const float* __restrict__ A_log)
{
    __shared__ float sB[CLEN * DSTATE];    // 8 KB
    int tid = threadIdx.x;
    int ch = blockIdx.x * 16 + (tid >> 4);   // 0..4095
    int n = tid & 15;
    int c = blockIdx.y;
    int b = ch >> 11;
    int d = ch & (DINNER - 1);

    const float* xd = g_xdbl + (size_t)(b * SEQL + c * CLEN) * XDBL_LD;
    for (int i = tid; i < CLEN * DSTATE; i += 256)
        sB[i] = xd[(i >> 4) * XDBL_LD + DTRANK + (i & 15)];
    __syncthreads();

    float a = -expf(A_log[d * DSTATE + n]);
    float h = 0.f, sd = 0.f;

    const __half* dptr = g_dh + (size_t)(b * SEQL + c * CLEN) * DINNER + d;
    const __half* uptr = g_uh + (size_t)(b * SEQL + c * CLEN) * DINNER + d;

    for (int t = 0; t < CLEN; t++) {
        float delta = __half2float(dptr[(size_t)t * DINNER]);
        float uv    = __half2float(uptr[(size_t)t * DINNER]);
        float Bn    = sB[(t << 4) | n];
        h = __expf(delta * a) * h + delta * uv * Bn;
        sd += delta;
    }
    size_t idx = ((size_t)(b * DINNER + d) * DSTATE + n);
    g_hend[idx * NCHUNK + c] = h;
    if (n == 0) g_sumd[(size_t)(b * DINNER + d) * NCHUNK + c] = sd;
}

// ---------------- chunked scan: phase 2 (inline combine + y), smem B+C ----------------
__global__ __launch_bounds__(256) void scan_phase2(
    const float* __restrict__ A_log, const float* __restrict__ Dp)
{
    __shared__ float sBC[CLEN * 2 * DSTATE];   // 16 KB: [t][0..15]=B, [t][16..31]=C
    int tid = threadIdx.x;
    int ch = blockIdx.x * 16 + (tid >> 4);
    int n = tid & 15;
    int c = blockIdx.y;
    int b = ch >> 11;
    int d = ch & (DINNER - 1);

    const float* xd = g_xdbl + (size_t)(b * SEQL + c * CLEN) * XDBL_LD;
    for (int i = tid; i < CLEN * 2 * DSTATE; i += 256)
        sBC[i] = xd[(i >> 5) * XDBL_LD + DTRANK + (i & 31)];
    __syncthreads();

    float a = -expf(A_log[d * DSTATE + n]);
    float Dd = Dp[d];

    // inline combine: h0 for this chunk = fold of previous chunks
    float h = 0.f;
    {
        size_t bi = ((size_t)(b * DINNER + d) * DSTATE + n) * NCHUNK;
        size_t bs = (size_t)(b * DINNER + d) * NCHUNK;
        for (int cc = 0; cc < c; cc++)
            h = __expf(a * g_sumd[bs + cc]) * h + g_hend[bi + cc];
    }

    const __half* dptr = g_dh  + (size_t)(b * SEQL + c * CLEN) * DINNER + d;
    const __half* uptr = g_uh  + (size_t)(b * SEQL + c * CLEN) * DINNER + d;
    const __half* zptr = g_zsh + (size_t)(b * SEQL + c * CLEN) * DINNER + d;
    __half* yh = g_yh + (size_t)(b * SEQL + c * CLEN) * DINNER + d;

    for (int t = 0; t < CLEN; t++) {
        float delta = __half2float(dptr[(size_t)t * DINNER]);
        float uv    = __half2float(uptr[(size_t)t * DINNER]);
        float Bn    = sBC[(t << 5) | n];
        float Cn    = sBC[(t << 5) | 16 | n];

        h = __expf(delta * a) * h + delta * uv * Bn;

        float p = h * Cn;
        p += __shfl_xor_sync(0xffffffffu, p, 8);
        p += __shfl_xor_sync(0xffffffffu, p, 4);
        p += __shfl_xor_sync(0xffffffffu, p, 2);
        p += __shfl_xor_sync(0xffffffffu, p, 1);

        if (n == 0) {
            float v = (p + uv * Dd) * __half2float(zptr[(size_t)t * DINNER]);
            yh[(size_t)t * DINNER] = __float2half_rn(v);
        }
    }
}

// ---------------- launch ----------------
extern "C" void kernel_launch(void* const* d_in, const int* in_sizes, int n_in,
                              void* d_out, int out_size)
{
    (void)in_sizes; (void)n_in; (void)out_size;
    const float* x     = (const float*)d_in[0];
    const float* W_in  = (const float*)d_in[1];
    const float* ck    = (const float*)d_in[2];
    const float* cb    = (const float*)d_in[3];
    const float* W_x   = (const float*)d_in[4];
    const float* W_dt  = (const float*)d_in[5];
    const float* b_dt  = (const float*)d_in[6];
    const float* W_out = (const float*)d_in[7];
    const float* A_log = (const float*)d_in[8];
    const float* Dp    = (const float*)d_in[9];
    float* out = (float*)d_out;

    cudaFuncSetAttribute((const void*)mma_gemm<0>, cudaFuncAttributeMaxDynamicSharedMemorySize, MG_SMEM);
    cudaFuncSetAttribute((const void*)mma_gemm<1>, cudaFuncAttributeMaxDynamicSharedMemorySize, MG_SMEM);
    cudaFuncSetAttribute((const void*)mma_gemm<3>, cudaFuncAttributeMaxDynamicSharedMemorySize, MG_SMEM);

    float *p_osplit;
    cudaGetSymbolAddress((void**)&p_osplit, g_osplit);
    __half *xh, *uh, *yh, *dth;
    __half *wint, *wxt, *wdtt, *wot;
    cudaGetSymbolAddress((void**)&xh, g_xh);
    cudaGetSymbolAddress((void**)&uh, g_uh);
    cudaGetSymbolAddress((void**)&yh, g_yh);
    cudaGetSymbolAddress((void**)&dth, g_dth);
    cudaGetSymbolAddress((void**)&wint, g_wint);
    cudaGetSymbolAddress((void**)&wxt, g_wxt);
    cudaGetSymbolAddress((void**)&wdtt, g_wdtt);
    cudaGetSymbolAddress((void**)&wot, g_wot);

    // 1: ALL prep (cvt x + 4 weight transposes)
    prep_all<<<8576, dim3(32, 8)>>>(x, W_in, W_out, W_x, W_dt);

    // 2: xz = x @ W_in : M=2048, N=4096, K=1024; u-half -> fp16 g_uraw, z -> silu -> g_zsh
    mma_gemm<3><<<dim3(32, 16, 1), 256, MG_SMEM>>>(
        xh, DMODEL, wint, DMODEL, nullptr, 0, DMODEL, 1, nullptr, 0);

    // 3: conv + silu -> fp16 uh (8 channels/thread)
    conv_silu<<<(NTOK * DINNER / 8) / 256, 256>>>(ck, cb);

    // 4: x_dbl = u @ W_x : M=2048, N=128(pad of 96), K=2048, split-K=8 -> fused reduce
    mma_gemm<0><<<dim3(1, 16, 8), 256, MG_SMEM>>>(
        uh, DINNER, wxt, DINNER, p_osplit, XDBL_LD, DINNER, 8, nullptr, NTOK * XDBL_LD);
    // 5:
    reduce8_xdbl<<<(NTOK * XDBL_LD / 4 + 255) / 256, 256>>>(p_osplit);

    // 6: delta = softplus(dt_lo @ W_dt + b_dt) : M=2048, N=2048, K=64 -> fp16 g_dh
    mma_gemm<1><<<dim3(16, 16, 1), 256, MG_SMEM>>>(
        dth, DTRANK, wdtt, DTRANK, nullptr, 0, DTRANK, 1, b_dt, 0);

    // 7,8: chunked selective scan (combine folded into phase 2)
    scan_phase1<<<dim3((BATCH * DINNER) / 16, NCHUNK), 256>>>(A_log);
    scan_phase2<<<dim3((BATCH * DINNER) / 16, NCHUNK), 256>>>(A_log, Dp);

    // 9,10: out = y @ W_out : M=2048, N=1024, K=2048, split-K=4 -> reduce
    mma_gemm<0><<<dim3(8, 16, 4), 256, MG_SMEM>>>(
        yh, DINNER, wot, DINNER, p_osplit, DMODEL, DINNER, 4, nullptr, NTOK * DMODEL);
    reduce4<<<(NTOK * DMODEL / 4 + 255) / 256, 256>>>(p_osplit, out, NTOK * DMODEL / 4);
}